// round 17
// baseline (speedup 1.0000x reference)
#include <cuda_runtime.h>
#include <cstdint>

#define N_MAX 25000
#define E_MAX 400000
#define CCH 64
#define ETHREADS 512
#define EGRID 148
#define GTILE 64
#define HSTR 68

static __device__ float4 d_x[N_MAX * CCH];   // up-projected  [N][C][4]
static __device__ float4 d_M[N_MAX * CCH];   // scatter accum [N][C][4]
static __device__ float  d_ef[E_MAX * 8];    // edge bessel feats
static __device__ float4 d_Y[E_MAX];         // sqrt3 * unit vec (w unused)
static __device__ float  d_U[4 * CCH];       // embW @ lin_up_W0[0]
static __device__ float  d_W0c[CCH * CCH];   // prod_lin_W0[0] @ lin_up_W0[1]
static __device__ float  d_W1c[CCH * CCH];   // prod_lin_W1[0] @ lin_up_W1[1]

__device__ __forceinline__ float silu_f(float v) {
    return v / (1.0f + __expf(-v));
}
__device__ __forceinline__ unsigned long long pack2(float x) {
    unsigned long long r;
    asm("mov.b64 %0, {%1, %1};" : "=l"(r) : "f"(x));
    return r;
}
__device__ __forceinline__ void fma2(unsigned long long &d, unsigned long long a, unsigned long long b) {
    asm("fma.rn.f32x2 %0, %1, %2, %0;" : "+l"(d) : "l"(a), "l"(b));
}
__device__ __forceinline__ float2 unpack2(unsigned long long v) {
    float2 r;
    asm("mov.b64 {%0, %1}, %2;" : "=f"(r.x), "=f"(r.y) : "l"(v));
    return r;
}

// ---------------------------------------------------------------------------
// Per-edge geometry: one sincosf + exact angle-addition recurrence
// ---------------------------------------------------------------------------
__global__ void k_geom(const float* __restrict__ pos, const int* __restrict__ ei, int E_) {
    int e = blockIdx.x * blockDim.x + threadIdx.x;
    if (e >= E_) return;
    int s = ei[e];
    int r_ = ei[E_ + e];
    float vx = pos[3*s + 0] - pos[3*r_ + 0];
    float vy = pos[3*s + 1] - pos[3*r_ + 1];
    float vz = pos[3*s + 2] - pos[3*r_ + 2];
    float rr = sqrtf(vx*vx + vy*vy + vz*vz);
    rr = fmaxf(rr, 1e-6f);
    float inv_r = 1.0f / rr;
    const float SQRT3 = 1.7320508075688772f;
    float4 Y;
    Y.x = SQRT3 * vx * inv_r;
    Y.y = SQRT3 * vy * inv_r;
    Y.z = SQRT3 * vz * inv_r;
    Y.w = 0.0f;
    d_Y[e] = Y;
    float x = rr * 0.2f;
    float x2 = x * x;
    float x6 = x2 * x2 * x2;
    float fc = 1.0f - 28.0f*x6 + 48.0f*x6*x - 21.0f*x6*x2;
    fc = (x < 1.0f) ? fc : 0.0f;
    const float BC = 0.6324555320336759f;      // sqrt(2/5)
    const float PI_O_R = 0.6283185307179586f;  // pi/5
    float pref = BC * inv_r * fc;
    float theta = PI_O_R * rr;
    float s1, c1;
    sincosf(theta, &s1, &c1);
    float ef[8];
    float sk = s1, ck = c1;
    ef[0] = pref * sk;
    #pragma unroll
    for (int k = 1; k < 8; k++) {
        float sn = sk * c1 + ck * s1;
        float cn = ck * c1 - sk * s1;
        sk = sn; ck = cn;
        ef[k] = pref * sk;
    }
    float4* dst = (float4*)(d_ef + (size_t)e * 8);
    dst[0] = make_float4(ef[0], ef[1], ef[2], ef[3]);
    dst[1] = make_float4(ef[4], ef[5], ef[6], ef[7]);
}

// ---------------------------------------------------------------------------
// Weight prep (17 blocks)
// ---------------------------------------------------------------------------
__global__ void __launch_bounds__(256) k_prepw(
    const float* __restrict__ embW, const float* __restrict__ LU0_l0,
    const float* __restrict__ PL0_l0, const float* __restrict__ LU0_l1,
    const float* __restrict__ PL1_l0, const float* __restrict__ LU1_l1)
{
    int tid = threadIdx.x;
    int b = blockIdx.x;
    if (b == 16) {
        int s = tid >> 6, j = tid & 63;
        float acc = 0.0f;
        for (int k = 0; k < 64; k++) acc += embW[s * 64 + k] * LU0_l0[k * 64 + j];
        d_U[tid] = acc;
        return;
    }
    int t = b * 256 + tid;
    int i = t >> 6, j = t & 63;
    float a0 = 0.0f, a1 = 0.0f;
    for (int k = 0; k < 64; k++) {
        a0 += PL0_l0[i * 64 + k] * LU0_l1[k * 64 + j];
        a1 += PL1_l0[i * 64 + k] * LU1_l1[k * 64 + j];
    }
    d_W0c[t] = a0;
    d_W1c[t] = a1;
}

// ---------------------------------------------------------------------------
// Layer-0 seed
// ---------------------------------------------------------------------------
__global__ void k_seed(const int* __restrict__ species, int N_) {
    int idx = blockIdx.x * blockDim.x + threadIdx.x;
    if (idx >= N_ * CCH) return;
    int n = idx >> 6, c = idx & 63;
    int sp = species[n];
    d_x[idx] = make_float4(d_U[sp * CCH + c], 0.0f, 0.0f, 0.0f);
    d_M[idx] = make_float4(0, 0, 0, 0);
}

// ---------------------------------------------------------------------------
// Persistent fused edge kernel: two independent 8-warp groups (named
// barriers), shared weights, EF double-buffered (registers), emission
// with deep gather prefetch (L0: all-8; L1: pipelined batches of 2).
// ---------------------------------------------------------------------------
#define SME_W1   0
#define SME_W2   512
#define SME_W3   4608
#define SME_GRP  25088
#define GRP_FL   9216    /* floats per group: gEF(512) + gHa(4352) + gHb(4352) */
#define SME_TOT  (SME_GRP + 2 * GRP_FL)   /* 43520 floats = 170 KB */
#define GO_EF    0
#define GO_HA    512
#define GO_HB    4864

template<bool FIRST>
__device__ __forceinline__ void emit_msg(float* dst, float4 xs, float4 Yv,
                                         float t0, float t1, float t2,
                                         float t3, float t4) {
    const float INV_SQRT3 = 0.5773502691896258f;
    const float INV_SQRT2 = 0.7071067811865475f;
    float m0, m1x, m1y, m1z;
    if (FIRST) {
        m0 = t0 * xs.x;
        float a = t1 * xs.x;
        m1x = a * Yv.x;
        m1y = a * Yv.y;
        m1z = a * Yv.z;
    } else {
        float dotv = xs.y * Yv.x + xs.z * Yv.y + xs.w * Yv.z;
        m0 = t0 * xs.x + t3 * dotv * INV_SQRT3;
        float cx = xs.z * Yv.z - xs.w * Yv.y;
        float cy = xs.w * Yv.x - xs.y * Yv.z;
        float cz = xs.y * Yv.y - xs.z * Yv.x;
        float a = t1 * xs.x;
        float t4s = t4 * INV_SQRT2;
        m1x = a * Yv.x + t2 * xs.y + t4s * cx;
        m1y = a * Yv.y + t2 * xs.z + t4s * cy;
        m1z = a * Yv.z + t2 * xs.w + t4s * cz;
    }
    asm volatile("red.global.add.v4.f32 [%0], {%1,%2,%3,%4};"
                 :: "l"(dst), "f"(m0), "f"(m1x), "f"(m1y), "f"(m1z)
                 : "memory");
}

template<bool FIRST>
__global__ void __launch_bounds__(ETHREADS, 1) k_edge(
    const int* __restrict__ ei,
    const float* __restrict__ W1g, const float* __restrict__ W2g,
    const float* __restrict__ W3g, int E_)
{
    extern __shared__ float sm[];
    float* sW1 = sm + SME_W1;
    float* sW2 = sm + SME_W2;
    float* sW3 = sm + SME_W3;
    const int tid = threadIdx.x;
    const int gid = tid >> 8;          // group 0 or 1
    const int ltid = tid & 255;        // thread within group
    const int lane = tid & 31;
    const int wl = ltid >> 5;          // warp within group, 0..7
    constexpr int NB = FIRST ? 2 : 5;

    float* GB = sm + SME_GRP + gid * GRP_FL;
    float* gEF = GB + GO_EF;           // [64][8]
    float* gHa = GB + GO_HA;           // [64][68]
    float* gHb = GB + GO_HB;           // [64][68]

    // shared one-time weight load
    for (int i = tid; i < 512; i += ETHREADS) sW1[i] = W1g[i];
    for (int i = tid; i < 4096; i += ETHREADS) sW2[i] = W2g[i];
    for (int i = tid; i < 20480; i += ETHREADS) sW3[i] = W3g[i];
    __syncthreads();

    const int barid = gid + 1;
    #define BARG() asm volatile("bar.sync %0, 256;" :: "r"(barid) : "memory")

    const long long tStep = (long long)EGRID * 2;
    int nTiles = (E_ + GTILE - 1) / GTILE;
    long long t0 = (long long)blockIdx.x * 2 + gid;

    // EF double-buffer: prefetch first tile into registers
    float4 efr0 = make_float4(0, 0, 0, 0), efr1 = efr0;
    if (ltid < 128) {
        long long e = t0 * GTILE + (ltid >> 1);
        if (t0 < nTiles && e < E_) {
            const float4* p = (const float4*)(d_ef + (size_t)e * 8);
            efr0 = p[0];
            // note: each staging thread handles ONE float4 (tid&1 selects half)
        }
    }
    // Actually stage per-thread: thread ltid<128 covers edge (ltid>>1), half (ltid&1)
    if (ltid < 128) {
        long long e = t0 * GTILE + (ltid >> 1);
        if (t0 < nTiles && e < E_)
            efr0 = ((const float4*)(d_ef))[e * 2 + (ltid & 1)];
        else
            efr0 = make_float4(0, 0, 0, 0);
    }

    for (long long t = t0; t < nTiles; t += tStep) {
        long long base = t * GTILE;

        BARG();   // prev tile fully consumed by this group
        if (ltid < 128) ((float4*)gEF)[ltid] = efr0;
        BARG();

        // Phase B: H1 = silu(EF @ W1)  [64x8]@[8x64], 16 outputs/thread
        #pragma unroll
        for (int i = 0; i < 16; i++) {
            int idx = ltid + 256 * i;
            int e = idx >> 6, j = idx & 63;
            float acc = 0.0f;
            #pragma unroll
            for (int k = 0; k < 8; k++) acc += gEF[e * 8 + k] * sW1[k * 64 + j];
            gHa[e * HSTR + j] = silu_f(acc);
        }

        // prefetch next tile's EF (hidden under C + D)
        if (ltid < 128) {
            long long tn = t + tStep;
            long long e = tn * GTILE + (ltid >> 1);
            if (tn < nTiles && e < E_)
                efr1 = ((const float4*)(d_ef))[e * 2 + (ltid & 1)];
            else
                efr1 = make_float4(0, 0, 0, 0);
        }
        BARG();

        // Phase C: H2 = silu(H1 @ W2), 4 edges x 4 cols, float2 K-batch
        {
            int e0 = (ltid >> 4) << 2;
            int j0 = (ltid & 15) << 2;
            unsigned long long acc[4][2] = {};
            #pragma unroll 2
            for (int cc = 0; cc < 64; cc += 2) {
                float2 a[4];
                #pragma unroll
                for (int i = 0; i < 4; i++)
                    a[i] = *(const float2*)&gHa[(e0 + i) * HSTR + cc];
                #pragma unroll
                for (int k = 0; k < 2; k++) {
                    const unsigned long long* bp =
                        (const unsigned long long*)&sW2[(cc + k) * 64 + j0];
                    unsigned long long b0 = bp[0], b1 = bp[1];
                    #pragma unroll
                    for (int i = 0; i < 4; i++) {
                        unsigned long long a2 = pack2(k ? a[i].y : a[i].x);
                        fma2(acc[i][0], a2, b0);
                        fma2(acc[i][1], a2, b1);
                    }
                }
            }
            #pragma unroll
            for (int i = 0; i < 4; i++) {
                float2 p0 = unpack2(acc[i][0]);
                float2 p1 = unpack2(acc[i][1]);
                float* dst = &gHb[(e0 + i) * HSTR + j0];
                dst[0] = silu_f(p0.x);
                dst[1] = silu_f(p0.y);
                dst[2] = silu_f(p1.x);
                dst[3] = silu_f(p1.y);
            }
        }
        BARG();

        // Phase D+E fused: warp owns 8 edges; thread owns a channel pair.
        {
            int eb = wl * 8;
            int cb = lane * 2;
            long long ge = base + eb + (lane & 7);
            int sv = 0, rv = -1;
            float yx = 0, yy = 0, yz = 0;
            if (ge < E_) {
                sv = ei[ge];
                rv = ei[E_ + ge];
                float4 y = d_Y[ge];
                yx = y.x; yy = y.y; yz = y.z;
            }

            unsigned long long acc[8][NB];
            #pragma unroll
            for (int ii = 0; ii < 8; ii++)
                #pragma unroll
                for (int p = 0; p < NB; p++) acc[ii][p] = 0ull;

            #pragma unroll 1
            for (int cc = 0; cc < 64; cc += 2) {
                float2 a[8];
                #pragma unroll
                for (int ii = 0; ii < 8; ii++)
                    a[ii] = *(const float2*)&gHb[(eb + ii) * HSTR + cc];
                #pragma unroll
                for (int k = 0; k < 2; k++) {
                    const float* wrow = &sW3[(cc + k) * 320 + cb];
                    unsigned long long b[NB];
                    #pragma unroll
                    for (int p = 0; p < NB; p++)
                        b[p] = *(const unsigned long long*)(wrow + 64 * p);
                    #pragma unroll
                    for (int ii = 0; ii < 8; ii++) {
                        unsigned long long a2 = pack2(k ? a[ii].y : a[ii].x);
                        #pragma unroll
                        for (int p = 0; p < NB; p++) fma2(acc[ii][p], a2, b[p]);
                    }
                }
            }

            if (FIRST) {
                // all-8 deep prefetch of xs (MLP=16), Yv shuffled at emit
                float4 xs0[8], xs1[8];
                int rr8[8];
                #pragma unroll
                for (int ii = 0; ii < 8; ii++) {
                    int s = __shfl_sync(0xffffffffu, sv, ii);
                    rr8[ii] = __shfl_sync(0xffffffffu, rv, ii);
                    const float4* xp = &d_x[(size_t)s * CCH + cb];
                    xs0[ii] = xp[0];
                    xs1[ii] = xp[1];
                }
                #pragma unroll
                for (int ii = 0; ii < 8; ii++) {
                    if (rr8[ii] < 0) continue;
                    float4 Yv;
                    Yv.x = __shfl_sync(0xffffffffu, yx, ii);
                    Yv.y = __shfl_sync(0xffffffffu, yy, ii);
                    Yv.z = __shfl_sync(0xffffffffu, yz, ii);
                    Yv.w = 0.0f;
                    float2 t0v = unpack2(acc[ii][0]);
                    float2 t1v = unpack2(acc[ii][1]);
                    float* dst = (float*)&d_M[(size_t)rr8[ii] * CCH + cb];
                    emit_msg<true>(dst,     xs0[ii], Yv, t0v.x, t1v.x, 0, 0, 0);
                    emit_msg<true>(dst + 4, xs1[ii], Yv, t0v.y, t1v.y, 0, 0, 0);
                }
            } else {
                // pipelined batches of 2: prefetch next during current emit
                float4 cx0[2], cx1[2];
                int crr[2];
                #pragma unroll
                for (int j = 0; j < 2; j++) {
                    int s = __shfl_sync(0xffffffffu, sv, j);
                    crr[j] = __shfl_sync(0xffffffffu, rv, j);
                    const float4* xp = &d_x[(size_t)s * CCH + cb];
                    cx0[j] = xp[0];
                    cx1[j] = xp[1];
                }
                #pragma unroll
                for (int bb = 0; bb < 4; bb++) {
                    float4 nx0[2], nx1[2];
                    int nrr[2];
                    if (bb < 3) {
                        #pragma unroll
                        for (int j = 0; j < 2; j++) {
                            int ii = (bb + 1) * 2 + j;
                            int s = __shfl_sync(0xffffffffu, sv, ii);
                            nrr[j] = __shfl_sync(0xffffffffu, rv, ii);
                            const float4* xp = &d_x[(size_t)s * CCH + cb];
                            nx0[j] = xp[0];
                            nx1[j] = xp[1];
                        }
                    }
                    #pragma unroll
                    for (int j = 0; j < 2; j++) {
                        int ii = bb * 2 + j;
                        if (crr[j] < 0) continue;
                        float4 Yv;
                        Yv.x = __shfl_sync(0xffffffffu, yx, ii);
                        Yv.y = __shfl_sync(0xffffffffu, yy, ii);
                        Yv.z = __shfl_sync(0xffffffffu, yz, ii);
                        Yv.w = 0.0f;
                        float2 t0v = unpack2(acc[ii][0]);
                        float2 t1v = unpack2(acc[ii][1]);
                        float2 t2v = unpack2(acc[ii][2]);
                        float2 t3v = unpack2(acc[ii][3]);
                        float2 t4v = unpack2(acc[ii][4]);
                        float* dst = (float*)&d_M[(size_t)crr[j] * CCH + cb];
                        emit_msg<false>(dst,     cx0[j], Yv, t0v.x, t1v.x, t2v.x, t3v.x, t4v.x);
                        emit_msg<false>(dst + 4, cx1[j], Yv, t0v.y, t1v.y, t2v.y, t3v.y, t4v.y);
                    }
                    if (bb < 3) {
                        #pragma unroll
                        for (int j = 0; j < 2; j++) {
                            cx0[j] = nx0[j];
                            cx1[j] = nx1[j];
                            crr[j] = nrr[j];
                        }
                    }
                }
            }
        }
        efr0 = efr1;   // rotate EF double-buffer
    }
    #undef BARG
}

// ---------------------------------------------------------------------------
// Fused post(l0)+up(l1) / final post
// ---------------------------------------------------------------------------
#define SMP_LW0 0
#define SMP_LW1 4096
#define SMP_PL0 8192
#define SMP_PL1 12288
#define SMP_PW0 16384
#define SMP_PW1 17152
#define SMP_A   17664
#define SMP_B   18688
#define SMP_TOT 19712   // floats

template<bool FINAL>
__global__ void __launch_bounds__(256) k_post(
    const int* __restrict__ species,
    const float* __restrict__ LW0g, const float* __restrict__ LW1g,
    const float* __restrict__ PW0g, const float* __restrict__ PW1g,
    const float* __restrict__ PL0g, const float* __restrict__ PL1g,
    float4* __restrict__ out, int N_)
{
    extern __shared__ float sm[];
    float* sLW0 = sm + SMP_LW0;
    float* sLW1 = sm + SMP_LW1;
    float* sPL0 = sm + SMP_PL0;
    float* sPL1 = sm + SMP_PL1;
    float* sPW0 = sm + SMP_PW0;
    float* sPW1 = sm + SMP_PW1;
    float4* sA = (float4*)(sm + SMP_A);
    float4* sB = (float4*)(sm + SMP_B);
    int tid = threadIdx.x;
    const float INV_SQRT3 = 0.5773502691896258f;
    for (int i = tid; i < 4096; i += 256) {
        sLW0[i] = LW0g[i];
        sLW1[i] = LW1g[i];
        sPL0[i] = PL0g[i];
        sPL1[i] = PL1g[i];
    }
    for (int i = tid; i < 768; i += 256) sPW0[i] = PW0g[i];
    for (int i = tid; i < 512; i += 256) sPW1[i] = PW1g[i];
    __syncthreads();

    int base = blockIdx.x * 64;
    int c = tid & 63, sub = tid >> 6;
    for (int g = 0; g < 16; g++) {
        int n = base + g * 4 + sub;
        bool act = n < N_;
        if (act) {
            float4 mv = d_M[(size_t)n * CCH + c];
            mv.x *= 0.0625f; mv.y *= 0.0625f; mv.z *= 0.0625f; mv.w *= 0.0625f;
            sA[sub * CCH + c] = mv;
        }
        __syncthreads();
        if (act) {
            float h0 = 0, h1x = 0, h1y = 0, h1z = 0;
            const float4* ar = &sA[sub * CCH];
            #pragma unroll 8
            for (int cc = 0; cc < 64; cc++) {
                float4 a = ar[cc];
                float w0 = sLW0[cc * 64 + c];
                float w1 = sLW1[cc * 64 + c];
                h0 += a.x * w0;
                h1x += a.y * w1;
                h1y += a.z * w1;
                h1z += a.w * w1;
            }
            int sp = species[n];
            float nrm = (h1x * h1x + h1y * h1y + h1z * h1z) * INV_SQRT3;
            const float* p0 = &sPW0[sp * 192 + c];
            float b0 = p0[0] * h0 + p0[64] * h0 * h0 + p0[128] * nrm;
            const float* p1 = &sPW1[sp * 128 + c];
            float q = p1[0] + p1[64] * h0;
            sB[sub * CCH + c] = make_float4(b0, q * h1x, q * h1y, q * h1z);
        }
        __syncthreads();
        if (act) {
            float o0 = 0, o1 = 0, o2 = 0, o3 = 0;
            const float4* br = &sB[sub * CCH];
            #pragma unroll 8
            for (int cc = 0; cc < 64; cc++) {
                float4 b = br[cc];
                float w0 = sPL0[cc * 64 + c];
                float w1 = sPL1[cc * 64 + c];
                o0 += b.x * w0;
                o1 += b.y * w1;
                o2 += b.z * w1;
                o3 += b.w * w1;
            }
            if (FINAL) {
                out[(size_t)n * CCH + c] = make_float4(o0, o1, o2, o3);
            } else {
                d_x[(size_t)n * CCH + c] = make_float4(o0, o1, o2, o3);
                d_M[(size_t)n * CCH + c] = make_float4(0, 0, 0, 0);
            }
        }
        __syncthreads();
    }
}

// ---------------------------------------------------------------------------
extern "C" void kernel_launch(void* const* d_in, const int* in_sizes, int n_in,
                              void* d_out, int out_size) {
    const float* positions    = (const float*)d_in[0];
    const int*   species      = (const int*)d_in[1];
    const int*   edge_index   = (const int*)d_in[2];
    const float* node_embed_W = (const float*)d_in[3];
    const float* lin_up_W0    = (const float*)d_in[4];
    const float* lin_up_W1    = (const float*)d_in[5];
    const float* mlp_W1       = (const float*)d_in[6];
    const float* mlp_W2       = (const float*)d_in[7];
    const float* mlp_W3       = (const float*)d_in[8];
    const float* lin_W0       = (const float*)d_in[9];
    const float* lin_W1       = (const float*)d_in[10];
    const float* prod_W0      = (const float*)d_in[11];
    const float* prod_W1      = (const float*)d_in[12];
    const float* prod_lin_W0  = (const float*)d_in[13];
    const float* prod_lin_W1  = (const float*)d_in[14];

    int N_ = in_sizes[0] / 3;
    int E_ = in_sizes[2] / 2;

    size_t smemE = (size_t)SME_TOT * 4;
    size_t smemP = (size_t)SMP_TOT * 4;
    cudaFuncSetAttribute(k_edge<true>,  cudaFuncAttributeMaxDynamicSharedMemorySize, (int)smemE);
    cudaFuncSetAttribute(k_edge<false>, cudaFuncAttributeMaxDynamicSharedMemorySize, (int)smemE);
    cudaFuncSetAttribute(k_post<true>,  cudaFuncAttributeMaxDynamicSharedMemorySize, (int)smemP);
    cudaFuncSetAttribute(k_post<false>, cudaFuncAttributeMaxDynamicSharedMemorySize, (int)smemP);

    k_geom<<<(E_ + 255) / 256, 256>>>(positions, edge_index, E_);
    k_prepw<<<17, 256>>>(node_embed_W, lin_up_W0,
                         prod_lin_W0, lin_up_W0 + 4096,
                         prod_lin_W1, lin_up_W1 + 4096);
    k_seed<<<(N_ * CCH + 255) / 256, 256>>>(species, N_);

    void* p0;
    void* p1;
    cudaGetSymbolAddress(&p0, d_W0c);
    cudaGetSymbolAddress(&p1, d_W1c);
    const float* W0c_sym = (const float*)p0;
    const float* W1c_sym = (const float*)p1;

    // layer 0
    k_edge<true><<<EGRID, ETHREADS, smemE>>>(edge_index, mlp_W1, mlp_W2, mlp_W3, E_);
    k_post<false><<<(N_ + 63) / 64, 256, smemP>>>(
        species, lin_W0, lin_W1, prod_W0, prod_W1,
        W0c_sym, W1c_sym, nullptr, N_);

    // layer 1
    k_edge<false><<<EGRID, ETHREADS, smemE>>>(
        edge_index, mlp_W1 + 512, mlp_W2 + 4096, mlp_W3 + 20480, E_);
    k_post<true><<<(N_ + 63) / 64, 256, smemP>>>(
        species, lin_W0 + 4096, lin_W1 + 4096,
        prod_W0 + 768, prod_W1 + 512,
        prod_lin_W0 + 4096, prod_lin_W1 + 4096,
        (float4*)d_out, N_);
}